// round 1
// baseline (speedup 1.0000x reference)
#include <cuda_runtime.h>
#include <cuda_bf16.h>
#include <math.h>

// Problem constants (shapes are fixed by the reference)
#define NMAX 100000
#define EMAX 1600000
#define IN_F 64
#define HID_F 16
#define OUT_F 40

// ---------------- scratch (device globals: allocation-free) ----------------
__device__ float g_dis[NMAX];            // degree -> d^{-1/2}
__device__ float g_norm[EMAX];           // per-edge -dis[row]*dis[col]
__device__ float g_Y[NMAX * 48];         // layer1: Y0|Y1|Y2 (16 each)
__device__ float g_acc1[NMAX * 32];      // Lhat(Y1) | Lhat(Y2)
__device__ float g_acc2[NMAX * 16];      // Lhat(Lhat(Y2))
__device__ float g_h[NMAX * 16];         // relu(out1)
__device__ float g_Z[NMAX * 120];        // layer2: Z0|Z1|Z2 (40 each)
__device__ float g_acc3[NMAX * 80];      // Lhat(Z1) | Lhat(Z2)
__device__ float g_acc4[NMAX * 40];      // Lhat(Lhat(Z2))

// ---------------- helpers ----------------
__device__ __forceinline__ void red_add_v4(float* addr, float a, float b, float c, float d) {
    asm volatile("red.global.add.v4.f32 [%0], {%1,%2,%3,%4};"
                 :: "l"(addr), "f"(a), "f"(b), "f"(c), "f"(d) : "memory");
}

__global__ void zero_kernel(float* __restrict__ p, int n4) {
    int i = blockIdx.x * blockDim.x + threadIdx.x;
    if (i < n4) ((float4*)p)[i] = make_float4(0.f, 0.f, 0.f, 0.f);
}

// degree accumulation: deg[row[e]] += 1
__global__ void deg_kernel(const int* __restrict__ row, int E) {
    int e = blockIdx.x * blockDim.x + threadIdx.x;
    if (e < E) atomicAdd(&g_dis[row[e]], 1.0f);
}

// dis[i] = deg>0 ? rsqrt(deg) : 0   (in place)
__global__ void dis_kernel(int N) {
    int i = blockIdx.x * blockDim.x + threadIdx.x;
    if (i < N) {
        float d = g_dis[i];
        g_dis[i] = (d > 0.f) ? rsqrtf(d) : 0.f;
    }
}

// norm[e] = -(dis[row]*dis[col])
__global__ void norm_kernel(const int* __restrict__ row, const int* __restrict__ col, int E) {
    int e = blockIdx.x * blockDim.x + threadIdx.x;
    if (e < E) g_norm[e] = -(g_dis[row[e]] * g_dis[col[e]]);
}

// ------------- GEMM1: Y[n][0..47] = x[n][0..63] @ W1[k][.][.]  -------------
// sW[i*48 + (k*16+j)] = W1[k][i][j]
__global__ void gemm1_kernel(const float* __restrict__ x, const float* __restrict__ W1, int N) {
    __shared__ float sW[IN_F * 48];
    for (int t = threadIdx.x; t < 3 * IN_F * HID_F; t += blockDim.x) {
        int k = t / (IN_F * HID_F);
        int r = t % (IN_F * HID_F);
        int i = r / HID_F, j = r % HID_F;
        sW[i * 48 + k * 16 + j] = W1[t];
    }
    __syncthreads();
    int warp = threadIdx.x >> 5, lane = threadIdx.x & 31;
    int nodeBase = (blockIdx.x * 8 + warp) * 16;
    for (int nn = 0; nn < 16; nn++) {
        int node = nodeBase + nn;
        if (node >= N) return;
        const float4* xr = (const float4*)(x + (size_t)node * IN_F);
        float a0 = 0.f, a1 = 0.f;
#pragma unroll
        for (int i4 = 0; i4 < 16; i4++) {
            float4 xv = xr[i4];
            int i = i4 * 4;
            a0 += xv.x * sW[(i    ) * 48 + lane] + xv.y * sW[(i + 1) * 48 + lane]
                + xv.z * sW[(i + 2) * 48 + lane] + xv.w * sW[(i + 3) * 48 + lane];
            if (lane < 16) {
                a1 += xv.x * sW[(i    ) * 48 + 32 + lane] + xv.y * sW[(i + 1) * 48 + 32 + lane]
                    + xv.z * sW[(i + 2) * 48 + 32 + lane] + xv.w * sW[(i + 3) * 48 + 32 + lane];
            }
        }
        g_Y[(size_t)node * 48 + lane] = a0;
        if (lane < 16) g_Y[(size_t)node * 48 + 32 + lane] = a1;
    }
}

// ------------- scatter: dst[col[e]][:] += norm[e] * src[row[e]][off:off+F] -------------
template <int F4, int SRC_STRIDE, int SRC_OFF, int DST_STRIDE>
__global__ void scatter_kernel(const int* __restrict__ row, const int* __restrict__ col,
                               const float* __restrict__ src, float* __restrict__ dst, int E) {
    int tid = blockIdx.x * blockDim.x + threadIdx.x;
    int e = tid / F4;
    if (e >= E) return;
    int ch = tid % F4;
    float w = g_norm[e];
    int r = row[e], c = col[e];
    float4 v = *(const float4*)(src + (size_t)r * SRC_STRIDE + SRC_OFF + ch * 4);
    red_add_v4(dst + (size_t)c * DST_STRIDE + ch * 4, w * v.x, w * v.y, w * v.z, w * v.w);
}

// ------------- combine1 + relu -> h -------------
__global__ void combine1_kernel(const float* __restrict__ b1, int N) {
    int tid = blockIdx.x * blockDim.x + threadIdx.x;
    if (tid >= N * HID_F) return;
    int n = tid >> 4, f = tid & 15;
    float v = g_Y[(size_t)n * 48 + f]          // Y0
            + g_acc1[(size_t)n * 32 + f]       // Lhat(Y1)
            + 2.f * g_acc2[tid]                // 2*Lhat(Lhat(Y2))
            - g_Y[(size_t)n * 48 + 32 + f]     // -Y2
            + b1[f];
    g_h[tid] = v > 0.f ? v : 0.f;
}

// ------------- GEMM2: Z[n][0..119] = h[n][0..15] @ W2 -------------
__global__ void gemm2_kernel(const float* __restrict__ W2, int N) {
    __shared__ float sW[HID_F * 120];
    __shared__ float sh[32 * HID_F];
    for (int t = threadIdx.x; t < 3 * HID_F * OUT_F; t += blockDim.x) {
        int k = t / (HID_F * OUT_F);
        int r = t % (HID_F * OUT_F);
        int i = r / OUT_F, j = r % OUT_F;
        sW[i * 120 + k * 40 + j] = W2[t];
    }
    int base = blockIdx.x * 32;
    for (int t = threadIdx.x; t < 32 * HID_F; t += blockDim.x) {
        int node = base + t / HID_F;
        sh[t] = (node < N) ? g_h[(size_t)node * HID_F + (t % HID_F)] : 0.f;
    }
    __syncthreads();
    int j = threadIdx.x;
    if (j >= 120) return;
    for (int nn = 0; nn < 32; nn++) {
        int node = base + nn;
        if (node >= N) break;
        float a = 0.f;
#pragma unroll
        for (int i = 0; i < HID_F; i++) a += sh[nn * HID_F + i] * sW[i * 120 + j];
        g_Z[(size_t)node * 120 + j] = a;
    }
}

// ------------- final combine + log_softmax -------------
__global__ void final_kernel(const float* __restrict__ b2, float* __restrict__ out, int N) {
    int node = blockIdx.x * (blockDim.x >> 5) + (threadIdx.x >> 5);
    int lane = threadIdx.x & 31;
    if (node >= N) return;
    size_t z = (size_t)node * 120, a3 = (size_t)node * 80, a4 = (size_t)node * 40;
    float v0 = g_Z[z + lane] + g_acc3[a3 + lane] + 2.f * g_acc4[a4 + lane]
             - g_Z[z + 80 + lane] + b2[lane];
    bool has1 = lane < 8;
    float v1 = 0.f;
    if (has1) {
        int f = lane + 32;
        v1 = g_Z[z + f] + g_acc3[a3 + f] + 2.f * g_acc4[a4 + f]
           - g_Z[z + 80 + f] + b2[f];
    }
    float m = has1 ? fmaxf(v0, v1) : v0;
#pragma unroll
    for (int s = 16; s; s >>= 1) m = fmaxf(m, __shfl_xor_sync(0xffffffffu, m, s));
    float sum = expf(v0 - m) + (has1 ? expf(v1 - m) : 0.f);
#pragma unroll
    for (int s = 16; s; s >>= 1) sum += __shfl_xor_sync(0xffffffffu, sum, s);
    float ls = m + logf(sum);
    out[a4 + lane] = v0 - ls;
    if (has1) out[a4 + lane + 32] = v1 - ls;
}

// ---------------- host launcher ----------------
static float* sym_addr(const void* sym) {
    void* p = nullptr;
    cudaGetSymbolAddress(&p, sym);
    return (float*)p;
}

extern "C" void kernel_launch(void* const* d_in, const int* in_sizes, int n_in,
                              void* d_out, int out_size) {
    const float* x  = (const float*)d_in[0];
    const int*   ei = (const int*)d_in[1];
    const float* W1 = (const float*)d_in[2];
    const float* b1 = (const float*)d_in[3];
    const float* W2 = (const float*)d_in[4];
    const float* b2 = (const float*)d_in[5];
    float* out = (float*)d_out;

    int N = in_sizes[0] / IN_F;
    int E = in_sizes[1] / 2;
    if (N > NMAX) N = NMAX;
    if (E > EMAX) E = EMAX;
    const int* row = ei;
    const int* col = ei + E;

    float* p_dis  = sym_addr(g_dis);
    float* p_Y    = sym_addr(g_Y);
    float* p_acc1 = sym_addr(g_acc1);
    float* p_acc2 = sym_addr(g_acc2);
    float* p_acc3 = sym_addr(g_acc3);
    float* p_acc4 = sym_addr(g_acc4);

    const int T = 256;
    auto blocks = [](long n, int t) { return (int)((n + t - 1) / t); };

    // zero scratch accumulators (+ degree)
    zero_kernel<<<blocks(N / 4 + 1, T), T>>>(p_dis, (N + 3) / 4);
    zero_kernel<<<blocks((long)N * 32 / 4, T), T>>>(p_acc1, N * 32 / 4);
    zero_kernel<<<blocks((long)N * 16 / 4, T), T>>>(p_acc2, N * 16 / 4);
    zero_kernel<<<blocks((long)N * 80 / 4, T), T>>>(p_acc3, N * 80 / 4);
    zero_kernel<<<blocks((long)N * 40 / 4, T), T>>>(p_acc4, N * 40 / 4);

    // normalization
    deg_kernel<<<blocks(E, T), T>>>(row, E);
    dis_kernel<<<blocks(N, T), T>>>(N);
    norm_kernel<<<blocks(E, T), T>>>(row, col, E);

    // layer 1
    gemm1_kernel<<<blocks((long)N, 128), 256>>>(x, W1, N);   // 128 nodes/block
    scatter_kernel<8, 48, 16, 32><<<blocks((long)E * 8, T), T>>>(row, col, p_Y, p_acc1, E);
    scatter_kernel<4, 32, 16, 16><<<blocks((long)E * 4, T), T>>>(row, col, p_acc1, p_acc2, E);
    combine1_kernel<<<blocks((long)N * 16, T), T>>>(b1, N);

    // layer 2
    gemm2_kernel<<<blocks((long)N, 32), 128>>>(W2, N);       // 32 nodes/block
    scatter_kernel<20, 120, 40, 80><<<blocks((long)E * 20, T), T>>>(row, col, sym_addr(g_Z), p_acc3, E);
    scatter_kernel<10, 80, 40, 40><<<blocks((long)E * 10, T), T>>>(row, col, p_acc3, p_acc4, E);
    final_kernel<<<blocks((long)N * 32, T), T>>>(b2, out, N);
}

// round 2
// speedup vs baseline: 1.7362x; 1.7362x over previous
#include <cuda_runtime.h>
#include <cuda_bf16.h>
#include <math.h>

#define NMAX 100000
#define EMAX 1600000
#define IN_F 64
#define HID_F 16
#define OUT_F 40

// ---------------- scratch (device globals: allocation-free) ----------------
__device__ float g_dis[NMAX];            // degree -> d^{-1/2}
__device__ float g_norm[EMAX];           // per-edge -dis[row]*dis[col]
__device__ float g_Y[NMAX * 48];         // layer1: Y0|Y1|Y2 (16 each)
__device__ float g_h[NMAX * 16];         // relu(out1)
__device__ float g_acc[NMAX * 64];       // A|B|C|D sections of N*16 each

#define ACC_A 0
#define ACC_B (NMAX * 16)
#define ACC_C (NMAX * 32)
#define ACC_D (NMAX * 48)

// ---------------- helpers ----------------
__device__ __forceinline__ void red_add_v4(float* addr, float a, float b, float c, float d) {
    asm volatile("red.global.add.v4.f32 [%0], {%1,%2,%3,%4};"
                 :: "l"(addr), "f"(a), "f"(b), "f"(c), "f"(d) : "memory");
}
__device__ __forceinline__ void red_add_f32(float* addr, float v) {
    asm volatile("red.global.add.f32 [%0], %1;" :: "l"(addr), "f"(v) : "memory");
}

__global__ void zero_kernel(float4* __restrict__ p, int n4) {
    int i = blockIdx.x * blockDim.x + threadIdx.x;
    if (i < n4) p[i] = make_float4(0.f, 0.f, 0.f, 0.f);
}

__global__ void deg_kernel(const int* __restrict__ row, int E) {
    int e = blockIdx.x * blockDim.x + threadIdx.x;
    if (e < E) red_add_f32(&g_dis[row[e]], 1.0f);
}

__global__ void dis_kernel(int N) {
    int i = blockIdx.x * blockDim.x + threadIdx.x;
    if (i < N) {
        float d = g_dis[i];
        g_dis[i] = (d > 0.f) ? rsqrtf(d) : 0.f;
    }
}

__global__ void norm_kernel(const int* __restrict__ row, const int* __restrict__ col, int E) {
    int e = blockIdx.x * blockDim.x + threadIdx.x;
    if (e < E) g_norm[e] = -(g_dis[row[e]] * g_dis[col[e]]);
}

// ------------- GEMM1: Y[n][0..47] = x[n][0..63] @ W1 (Y0|Y1|Y2) -------------
__global__ void gemm1_kernel(const float* __restrict__ x, const float* __restrict__ W1, int N) {
    __shared__ float sW[IN_F * 48];
    for (int t = threadIdx.x; t < 3 * IN_F * HID_F; t += blockDim.x) {
        int k = t / (IN_F * HID_F);
        int r = t % (IN_F * HID_F);
        int i = r / HID_F, j = r % HID_F;
        sW[i * 48 + k * 16 + j] = W1[t];
    }
    __syncthreads();
    int warp = threadIdx.x >> 5, lane = threadIdx.x & 31;
    int nodeBase = (blockIdx.x * 8 + warp) * 16;
    for (int nn = 0; nn < 16; nn++) {
        int node = nodeBase + nn;
        if (node >= N) return;
        const float4* xr = (const float4*)(x + (size_t)node * IN_F);
        float a0 = 0.f, a1 = 0.f;
#pragma unroll
        for (int i4 = 0; i4 < 16; i4++) {
            float4 xv = xr[i4];
            int i = i4 * 4;
            a0 += xv.x * sW[(i    ) * 48 + lane] + xv.y * sW[(i + 1) * 48 + lane]
                + xv.z * sW[(i + 2) * 48 + lane] + xv.w * sW[(i + 3) * 48 + lane];
            if (lane < 16) {
                a1 += xv.x * sW[(i    ) * 48 + 32 + lane] + xv.y * sW[(i + 1) * 48 + 32 + lane]
                    + xv.z * sW[(i + 2) * 48 + 32 + lane] + xv.w * sW[(i + 3) * 48 + 32 + lane];
            }
        }
        g_Y[(size_t)node * 48 + lane] = a0;
        if (lane < 16) g_Y[(size_t)node * 48 + 32 + lane] = a1;
    }
}

// ------------- scatter (F=16): dst[col[e]][:] += norm[e]*src[row[e]][off:off+16] ---------
template <int SRC_STRIDE, int SRC_OFF>
__global__ void scatter16(const int* __restrict__ row, const int* __restrict__ col,
                          const float* __restrict__ src, float* __restrict__ dst, int E) {
    int tid = blockIdx.x * blockDim.x + threadIdx.x;
    int e = tid >> 2;
    if (e >= E) return;
    int ch = tid & 3;
    float w = g_norm[e];
    int r = row[e], c = col[e];
    float4 v = *(const float4*)(src + (size_t)r * SRC_STRIDE + SRC_OFF + ch * 4);
    red_add_v4(dst + (size_t)c * 16 + ch * 4, w * v.x, w * v.y, w * v.z, w * v.w);
}

// ------------- axpy: accA = Y1 + 2*accA (in place) -------------
__global__ void axpy_kernel(int N) {
    int tid = blockIdx.x * blockDim.x + threadIdx.x;
    if (tid >= N * HID_F) return;
    int n = tid >> 4, f = tid & 15;
    g_acc[ACC_A + tid] = g_Y[(size_t)n * 48 + 16 + f] + 2.f * g_acc[ACC_A + tid];
}

// ------------- combine1 + relu -> h : h = relu(Y0 - Y2 + accB + b1) -------------
__global__ void combine1_kernel(const float* __restrict__ b1, int N) {
    int tid = blockIdx.x * blockDim.x + threadIdx.x;
    if (tid >= N * HID_F) return;
    int n = tid >> 4, f = tid & 15;
    float v = g_Y[(size_t)n * 48 + f]
            - g_Y[(size_t)n * 48 + 32 + f]
            + g_acc[ACC_B + tid]
            + b1[f];
    g_h[tid] = v > 0.f ? v : 0.f;
}

// ------------- final fused GEMM + bias + log_softmax -------------
// out[n] = logsoftmax( h[n]@(W2[0]-W2[2]) + C[n]@W2[1] + 2*D[n]@W2[2] + b2 )
__global__ void final_kernel(const float* __restrict__ W2, const float* __restrict__ b2,
                             float* __restrict__ out, int N) {
    __shared__ float sW[48 * 40];     // combined weight, rows: h | C | D
    __shared__ float sb[40];
    for (int t = threadIdx.x; t < HID_F * OUT_F; t += blockDim.x) {
        sW[t]                      = W2[t] - W2[2 * 640 + t];   // W2[0]-W2[2]
        sW[16 * 40 + t]            = W2[640 + t];               // W2[1]
        sW[32 * 40 + t]            = 2.f * W2[2 * 640 + t];     // 2*W2[2]
    }
    if (threadIdx.x < OUT_F) sb[threadIdx.x] = b2[threadIdx.x];
    __syncthreads();

    int n = blockIdx.x * blockDim.x + threadIdx.x;
    if (n >= N) return;

    float4 acc[10];
#pragma unroll
    for (int jj = 0; jj < 10; jj++)
        acc[jj] = make_float4(sb[jj*4], sb[jj*4+1], sb[jj*4+2], sb[jj*4+3]);

    const float4* sW4 = (const float4*)sW;   // [48][10]

    const float* srcs[3] = { g_h + (size_t)n * 16,
                             g_acc + ACC_C + (size_t)n * 16,
                             g_acc + ACC_D + (size_t)n * 16 };
#pragma unroll
    for (int b = 0; b < 3; b++) {
        float4 f4[4];
        const float4* s = (const float4*)srcs[b];
#pragma unroll
        for (int q = 0; q < 4; q++) f4[q] = s[q];
        const float* f = (const float*)f4;
#pragma unroll
        for (int i = 0; i < 16; i++) {
            float fv = f[i];
            const float4* wrow = sW4 + (b * 16 + i) * 10;
#pragma unroll
            for (int jj = 0; jj < 10; jj++) {
                float4 w = wrow[jj];
                acc[jj].x += fv * w.x; acc[jj].y += fv * w.y;
                acc[jj].z += fv * w.z; acc[jj].w += fv * w.w;
            }
        }
    }

    // log_softmax over 40 values
    float* a = (float*)acc;
    float m = a[0];
#pragma unroll
    for (int j = 1; j < 40; j++) m = fmaxf(m, a[j]);
    float sum = 0.f;
#pragma unroll
    for (int j = 0; j < 40; j++) sum += __expf(a[j] - m);
    float ls = m + __logf(sum);
    float* o = out + (size_t)n * 40;
#pragma unroll
    for (int jj = 0; jj < 10; jj++) {
        float4 v = acc[jj];
        v.x -= ls; v.y -= ls; v.z -= ls; v.w -= ls;
        ((float4*)o)[jj] = v;
    }
}

// ---------------- host launcher ----------------
static float* sym_addr(const void* sym) {
    void* p = nullptr;
    cudaGetSymbolAddress(&p, sym);
    return (float*)p;
}

extern "C" void kernel_launch(void* const* d_in, const int* in_sizes, int n_in,
                              void* d_out, int out_size) {
    const float* x  = (const float*)d_in[0];
    const int*   ei = (const int*)d_in[1];
    const float* W1 = (const float*)d_in[2];
    const float* b1 = (const float*)d_in[3];
    const float* W2 = (const float*)d_in[4];
    const float* b2 = (const float*)d_in[5];
    float* out = (float*)d_out;

    int N = in_sizes[0] / IN_F;
    int E = in_sizes[1] / 2;
    if (N > NMAX) N = NMAX;
    if (E > EMAX) E = EMAX;
    const int* row = ei;
    const int* col = ei + E;

    float* p_dis = sym_addr(g_dis);
    float* p_Y   = sym_addr(g_Y);
    float* p_h   = sym_addr(g_h);
    float* p_acc = sym_addr(g_acc);

    const int T = 256;
    auto blocks = [](long n, int t) { return (int)((n + t - 1) / t); };

    // zero: g_dis and all 4 acc sections
    zero_kernel<<<blocks((N + 3) / 4, T), T>>>((float4*)p_dis, (N + 3) / 4);
    zero_kernel<<<blocks((long)NMAX * 16, T), T>>>((float4*)p_acc, NMAX * 16);

    // normalization
    deg_kernel<<<blocks(E, T), T>>>(row, E);
    dis_kernel<<<blocks(N, T), T>>>(N);
    norm_kernel<<<blocks(E, T), T>>>(row, col, E);

    // layer 1: transform-first, then two F=16 edge passes
    gemm1_kernel<<<blocks((long)N, 128), 256>>>(x, W1, N);
    scatter16<48, 32><<<blocks((long)E * 4, T), T>>>(row, col, p_Y, p_acc + ACC_A, E);   // A = Lhat(Y2)
    axpy_kernel<<<blocks((long)N * 16, T), T>>>(N);                                      // A = Y1 + 2A
    scatter16<16, 0><<<blocks((long)E * 4, T), T>>>(row, col, p_acc + ACC_A, p_acc + ACC_B, E); // B = Lhat(A)
    combine1_kernel<<<blocks((long)N * 16, T), T>>>(b1, N);                              // h

    // layer 2: propagate-first (two F=16 passes), then fused GEMM+softmax
    scatter16<16, 0><<<blocks((long)E * 4, T), T>>>(row, col, p_h, p_acc + ACC_C, E);    // C = Lhat(h)
    scatter16<16, 0><<<blocks((long)E * 4, T), T>>>(row, col, p_acc + ACC_C, p_acc + ACC_D, E); // D = Lhat(C)
    final_kernel<<<blocks((long)N, T), T>>>(W2, b2, out, N);
}

// round 3
// speedup vs baseline: 1.8865x; 1.0866x over previous
#include <cuda_runtime.h>
#include <cuda_bf16.h>
#include <math.h>

#define NMAX 100000
#define EMAX 1600000
#define IN_F 64
#define HID_F 16
#define OUT_F 40
#define SCAN_CHUNK 2048
#define NB_MAX 64

// ---------------- scratch (device globals: allocation-free) ----------------
__device__ float g_dis[NMAX];            // out-degree -> d^{-1/2}
__device__ int   g_cnt[NMAX];            // in-degree (histogram by col)
__device__ int   g_off[NMAX];            // CSR offsets (by col)
__device__ int   g_cur[NMAX];            // fill cursors
__device__ int   g_part[NB_MAX];         // scan partials
__device__ int2  g_edge[EMAX];           // (src_row, norm_bits) sorted by dst
__device__ float g_Y[NMAX * 48];         // layer1: Y0|Y1|Y2 (16 each)
__device__ float g_h[NMAX * 16];         // relu(out1)
__device__ float g_acc[NMAX * 48];       // A|C|D sections of N*16 each

#define ACC_A 0
#define ACC_C (NMAX * 16)
#define ACC_D (NMAX * 32)

__device__ __forceinline__ void red_add_f32(float* addr, float v) {
    asm volatile("red.global.add.f32 [%0], %1;" :: "l"(addr), "f"(v) : "memory");
}

// ---------------- init: zero deg + histogram counters ----------------
__global__ void init_kernel(int N) {
    int i = blockIdx.x * blockDim.x + threadIdx.x;
    if (i < N) { g_dis[i] = 0.f; g_cnt[i] = 0; }
}

// ---------------- hist: out-degree (row) + in-degree (col) ----------------
__global__ void hist_kernel(const int* __restrict__ row, const int* __restrict__ col, int E) {
    int e = blockIdx.x * blockDim.x + threadIdx.x;
    if (e < E) {
        red_add_f32(&g_dis[row[e]], 1.0f);
        atomicAdd(&g_cnt[col[e]], 1);
    }
}

__global__ void dis_kernel(int N) {
    int i = blockIdx.x * blockDim.x + threadIdx.x;
    if (i < N) {
        float d = g_dis[i];
        g_dis[i] = (d > 0.f) ? rsqrtf(d) : 0.f;
    }
}

// ---------------- 3-phase exclusive scan of g_cnt -> g_off (and g_cur) -------------
__global__ void scan1_kernel(int N) {      // per-block partial sums
    __shared__ int s[256];
    int base = blockIdx.x * SCAN_CHUNK;
    int sum = 0;
    for (int i = threadIdx.x; i < SCAN_CHUNK; i += 256) {
        int idx = base + i;
        sum += (idx < N) ? g_cnt[idx] : 0;
    }
    s[threadIdx.x] = sum;
    __syncthreads();
    for (int st = 128; st; st >>= 1) {
        if (threadIdx.x < st) s[threadIdx.x] += s[threadIdx.x + st];
        __syncthreads();
    }
    if (threadIdx.x == 0) g_part[blockIdx.x] = s[0];
}

__global__ void scan2_kernel(int NB) {     // exclusive scan of partials (tiny)
    if (threadIdx.x == 0 && blockIdx.x == 0) {
        int run = 0;
        for (int b = 0; b < NB; b++) { int v = g_part[b]; g_part[b] = run; run += v; }
    }
}

__global__ void scan3_kernel(int N) {      // per-block exclusive scan + offset
    __shared__ int wsum[8];
    int lane = threadIdx.x & 31, wid = threadIdx.x >> 5;
    int base = blockIdx.x * SCAN_CHUNK + threadIdx.x * 8;
    int v[8];
    int sum = 0;
#pragma unroll
    for (int k = 0; k < 8; k++) {
        int idx = base + k;
        v[k] = (idx < N) ? g_cnt[idx] : 0;
        sum += v[k];
    }
    // warp inclusive scan of per-thread sums
    int isum = sum;
#pragma unroll
    for (int d = 1; d < 32; d <<= 1) {
        int t = __shfl_up_sync(0xffffffffu, isum, d);
        if (lane >= d) isum += t;
    }
    if (lane == 31) wsum[wid] = isum;
    __syncthreads();
    if (threadIdx.x == 0) {
        int run = 0;
        for (int w = 0; w < 8; w++) { int t = wsum[w]; wsum[w] = run; run += t; }
    }
    __syncthreads();
    int excl = (isum - sum) + wsum[wid] + g_part[blockIdx.x];
#pragma unroll
    for (int k = 0; k < 8; k++) {
        int idx = base + k;
        if (idx < N) { g_off[idx] = excl; g_cur[idx] = excl; }
        excl += v[k];
    }
}

// ---------------- fill: CSR records (row, norm) bucketed by col ----------------
__global__ void fill_kernel(const int* __restrict__ row, const int* __restrict__ col, int E) {
    int e = blockIdx.x * blockDim.x + threadIdx.x;
    if (e >= E) return;
    int r = row[e], c = col[e];
    float nrm = -(g_dis[r] * g_dis[c]);
    int pos = atomicAdd(&g_cur[c], 1);
    g_edge[pos] = make_int2(r, __float_as_int(nrm));
}

// ------------- GEMM1: Y[n][0..47] = x[n][0..63] @ W1 (Y0|Y1|Y2) -------------
__global__ void gemm1_kernel(const float* __restrict__ x, const float* __restrict__ W1, int N) {
    __shared__ float sW[IN_F * 48];
    for (int t = threadIdx.x; t < 3 * IN_F * HID_F; t += blockDim.x) {
        int k = t / (IN_F * HID_F);
        int r = t % (IN_F * HID_F);
        int i = r / HID_F, j = r % HID_F;
        sW[i * 48 + k * 16 + j] = W1[t];
    }
    __syncthreads();
    int warp = threadIdx.x >> 5, lane = threadIdx.x & 31;
    int nodeBase = (blockIdx.x * 8 + warp) * 16;
    for (int nn = 0; nn < 16; nn++) {
        int node = nodeBase + nn;
        if (node >= N) return;
        const float4* xr = (const float4*)(x + (size_t)node * IN_F);
        float a0 = 0.f, a1 = 0.f;
#pragma unroll
        for (int i4 = 0; i4 < 16; i4++) {
            float4 xv = xr[i4];
            int i = i4 * 4;
            a0 += xv.x * sW[(i    ) * 48 + lane] + xv.y * sW[(i + 1) * 48 + lane]
                + xv.z * sW[(i + 2) * 48 + lane] + xv.w * sW[(i + 3) * 48 + lane];
            if (lane < 16) {
                a1 += xv.x * sW[(i    ) * 48 + 32 + lane] + xv.y * sW[(i + 1) * 48 + 32 + lane]
                    + xv.z * sW[(i + 2) * 48 + 32 + lane] + xv.w * sW[(i + 3) * 48 + 32 + lane];
            }
        }
        g_Y[(size_t)node * 48 + lane] = a0;
        if (lane < 16) g_Y[(size_t)node * 48 + 32 + lane] = a1;
    }
}

// ------------- CSR gather Lhat pass, F=16, 4 threads/node -------------
// EPI 0: dst = acc
// EPI 1: dst = Y1 + 2*acc            (A = Y1 + 2*Lhat(Y2))
// EPI 2: dst = relu(Y0 - Y2 + acc + bias)   (h)
template <int SSTR, int SOFF, int EPI>
__global__ void gather16(const float* __restrict__ src, float* __restrict__ dst,
                         const float* __restrict__ bias, int N) {
    int tid = blockIdx.x * blockDim.x + threadIdx.x;
    int n = tid >> 2;
    if (n >= N) return;
    int ch = tid & 3;
    int beg = g_off[n], cnt = g_cnt[n];
    const int2* ep = g_edge + beg;
    float ax = 0.f, ay = 0.f, az = 0.f, aw = 0.f;
    int i = 0;
    for (; i + 2 <= cnt; i += 2) {
        int2 e0 = ep[i], e1 = ep[i + 1];
        float w0 = __int_as_float(e0.y), w1 = __int_as_float(e1.y);
        float4 v0 = *(const float4*)(src + (size_t)e0.x * SSTR + SOFF + ch * 4);
        float4 v1 = *(const float4*)(src + (size_t)e1.x * SSTR + SOFF + ch * 4);
        ax += w0 * v0.x; ay += w0 * v0.y; az += w0 * v0.z; aw += w0 * v0.w;
        ax += w1 * v1.x; ay += w1 * v1.y; az += w1 * v1.z; aw += w1 * v1.w;
    }
    if (i < cnt) {
        int2 e0 = ep[i];
        float w0 = __int_as_float(e0.y);
        float4 v0 = *(const float4*)(src + (size_t)e0.x * SSTR + SOFF + ch * 4);
        ax += w0 * v0.x; ay += w0 * v0.y; az += w0 * v0.z; aw += w0 * v0.w;
    }
    float4 r;
    if (EPI == 0) {
        r = make_float4(ax, ay, az, aw);
    } else if (EPI == 1) {
        float4 y1 = *(const float4*)(g_Y + (size_t)n * 48 + 16 + ch * 4);
        r = make_float4(y1.x + 2.f * ax, y1.y + 2.f * ay, y1.z + 2.f * az, y1.w + 2.f * aw);
    } else {
        float4 y0 = *(const float4*)(g_Y + (size_t)n * 48 + ch * 4);
        float4 y2 = *(const float4*)(g_Y + (size_t)n * 48 + 32 + ch * 4);
        float4 b  = *(const float4*)(bias + ch * 4);
        r.x = y0.x - y2.x + ax + b.x; r.y = y0.y - y2.y + ay + b.y;
        r.z = y0.z - y2.z + az + b.z; r.w = y0.w - y2.w + aw + b.w;
        r.x = fmaxf(r.x, 0.f); r.y = fmaxf(r.y, 0.f);
        r.z = fmaxf(r.z, 0.f); r.w = fmaxf(r.w, 0.f);
    }
    *(float4*)(dst + (size_t)n * 16 + ch * 4) = r;
}

// ------------- final fused GEMM + bias + log_softmax -------------
__global__ void final_kernel(const float* __restrict__ W2, const float* __restrict__ b2,
                             float* __restrict__ out, int N) {
    __shared__ float sW[48 * 40];
    __shared__ float sb[40];
    for (int t = threadIdx.x; t < HID_F * OUT_F; t += blockDim.x) {
        sW[t]           = W2[t] - W2[2 * 640 + t];   // W2[0]-W2[2]
        sW[16 * 40 + t] = W2[640 + t];               // W2[1]
        sW[32 * 40 + t] = 2.f * W2[2 * 640 + t];     // 2*W2[2]
    }
    if (threadIdx.x < OUT_F) sb[threadIdx.x] = b2[threadIdx.x];
    __syncthreads();

    int n = blockIdx.x * blockDim.x + threadIdx.x;
    if (n >= N) return;

    float4 acc[10];
#pragma unroll
    for (int jj = 0; jj < 10; jj++)
        acc[jj] = make_float4(sb[jj*4], sb[jj*4+1], sb[jj*4+2], sb[jj*4+3]);

    const float4* sW4 = (const float4*)sW;

    const float* srcs[3] = { g_h + (size_t)n * 16,
                             g_acc + ACC_C + (size_t)n * 16,
                             g_acc + ACC_D + (size_t)n * 16 };
#pragma unroll
    for (int b = 0; b < 3; b++) {
        float4 f4[4];
        const float4* s = (const float4*)srcs[b];
#pragma unroll
        for (int q = 0; q < 4; q++) f4[q] = s[q];
        const float* f = (const float*)f4;
#pragma unroll
        for (int i = 0; i < 16; i++) {
            float fv = f[i];
            const float4* wrow = sW4 + (b * 16 + i) * 10;
#pragma unroll
            for (int jj = 0; jj < 10; jj++) {
                float4 w = wrow[jj];
                acc[jj].x += fv * w.x; acc[jj].y += fv * w.y;
                acc[jj].z += fv * w.z; acc[jj].w += fv * w.w;
            }
        }
    }

    float* a = (float*)acc;
    float m = a[0];
#pragma unroll
    for (int j = 1; j < 40; j++) m = fmaxf(m, a[j]);
    float sum = 0.f;
#pragma unroll
    for (int j = 0; j < 40; j++) sum += __expf(a[j] - m);
    float ls = m + __logf(sum);
    float* o = out + (size_t)n * 40;
#pragma unroll
    for (int jj = 0; jj < 10; jj++) {
        float4 v = acc[jj];
        v.x -= ls; v.y -= ls; v.z -= ls; v.w -= ls;
        ((float4*)o)[jj] = v;
    }
}

// ---------------- host launcher ----------------
static float* sym_addr(const void* sym) {
    void* p = nullptr;
    cudaGetSymbolAddress(&p, sym);
    return (float*)p;
}

extern "C" void kernel_launch(void* const* d_in, const int* in_sizes, int n_in,
                              void* d_out, int out_size) {
    const float* x  = (const float*)d_in[0];
    const int*   ei = (const int*)d_in[1];
    const float* W1 = (const float*)d_in[2];
    const float* b1 = (const float*)d_in[3];
    const float* W2 = (const float*)d_in[4];
    const float* b2 = (const float*)d_in[5];
    float* out = (float*)d_out;

    int N = in_sizes[0] / IN_F;
    int E = in_sizes[1] / 2;
    if (N > NMAX) N = NMAX;
    if (E > EMAX) E = EMAX;
    const int* row = ei;
    const int* col = ei + E;

    float* p_Y   = sym_addr(g_Y);
    float* p_h   = sym_addr(g_h);
    float* p_acc = sym_addr(g_acc);

    const int T = 256;
    auto blocks = [](long n, int t) { return (int)((n + t - 1) / t); };
    int NB = (N + SCAN_CHUNK - 1) / SCAN_CHUNK;

    // CSR build
    init_kernel<<<blocks(N, T), T>>>(N);
    hist_kernel<<<blocks(E, T), T>>>(row, col, E);
    dis_kernel<<<blocks(N, T), T>>>(N);
    scan1_kernel<<<NB, 256>>>(N);
    scan2_kernel<<<1, 32>>>(NB);
    scan3_kernel<<<NB, 256>>>(N);
    fill_kernel<<<blocks(E, T), T>>>(row, col, E);

    // layer 1
    gemm1_kernel<<<blocks((long)N, 128), 256>>>(x, W1, N);
    gather16<48, 32, 1><<<blocks((long)N * 4, T), T>>>(p_Y, p_acc + ACC_A, nullptr, N);          // A = Y1 + 2*Lhat(Y2)
    gather16<16, 0, 2><<<blocks((long)N * 4, T), T>>>(p_acc + ACC_A, p_h, b1, N);                // h = relu(Y0-Y2+Lhat(A)+b1)

    // layer 2
    gather16<16, 0, 0><<<blocks((long)N * 4, T), T>>>(p_h, p_acc + ACC_C, nullptr, N);           // C = Lhat(h)
    gather16<16, 0, 0><<<blocks((long)N * 4, T), T>>>(p_acc + ACC_C, p_acc + ACC_D, nullptr, N); // D = Lhat(C)
    final_kernel<<<blocks((long)N, T), T>>>(W2, b2, out, N);
}

// round 4
// speedup vs baseline: 1.9386x; 1.0276x over previous
#include <cuda_runtime.h>
#include <cuda_bf16.h>
#include <math.h>

#define NMAX 100000
#define EMAX 1600000
#define IN_F 64
#define HID_F 16
#define OUT_F 40
#define ROUND4(x) (((x) + 3) & ~3)

// ---------------- scratch (device globals: allocation-free) ----------------
__device__ float g_dis[NMAX];                 // out-degree -> d^{-1/2}
__device__ int   g_cnt[NMAX];                 // in-degree (by col)
__device__ int   g_off[NMAX];                 // padded CSR offsets (by col)
__device__ int   g_cur[NMAX];                 // fill cursors
__device__ int   g_total;                     // allocation cursor
__device__ __align__(16) int2 g_edge[EMAX + 4 * NMAX];  // (src, dis[src]) padded segments
__device__ float g_Y[NMAX * 48];              // layer1: Y0|Y1|Y2 (16 each)
__device__ float g_h[NMAX * 16];              // relu(out1)
__device__ float g_acc[NMAX * 48];            // A|C|D sections of N*16 each

#define ACC_A 0
#define ACC_C (NMAX * 16)
#define ACC_D (NMAX * 32)

__device__ __forceinline__ void red_add_f32(float* addr, float v) {
    asm volatile("red.global.add.f32 [%0], %1;" :: "l"(addr), "f"(v) : "memory");
}
__device__ __forceinline__ void red_add_s32(int* addr, int v) {
    asm volatile("red.global.add.s32 [%0], %1;" :: "l"(addr), "r"(v) : "memory");
}

// ---------------- init ----------------
__global__ void init_kernel(int N) {
    int i = blockIdx.x * blockDim.x + threadIdx.x;
    if (i < N) { g_dis[i] = 0.f; g_cnt[i] = 0; }
    if (i == 0) g_total = 0;
}

// ---------------- hist: out-degree (row) + in-degree (col) ----------------
__global__ void hist_kernel(const int* __restrict__ row, const int* __restrict__ col, int E) {
    int e = blockIdx.x * blockDim.x + threadIdx.x;
    if (e < E) {
        red_add_f32(&g_dis[row[e]], 1.0f);
        red_add_s32(&g_cnt[col[e]], 1);
    }
}

// ---------------- alloc: warp-aggregated segment allocation + pad + dis ----------------
__global__ void alloc_kernel(int N) {
    int i = blockIdx.x * blockDim.x + threadIdx.x;
    int lane = threadIdx.x & 31;
    int cnt = 0, cnt4 = 0;
    if (i < N) { cnt = g_cnt[i]; cnt4 = ROUND4(cnt); }
    // warp inclusive scan of cnt4
    int incl = cnt4;
#pragma unroll
    for (int d = 1; d < 32; d <<= 1) {
        int t = __shfl_up_sync(0xffffffffu, incl, d);
        if (lane >= d) incl += t;
    }
    int base = 0;
    if (lane == 31) base = atomicAdd(&g_total, incl);
    base = __shfl_sync(0xffffffffu, base, 31);
    if (i < N) {
        int off = base + incl - cnt4;
        g_off[i] = off;
        g_cur[i] = off;
        // zero-weight dummy pads
        for (int p = off + cnt; p < off + cnt4; p++) g_edge[p] = make_int2(0, 0);
        float d = g_dis[i];
        g_dis[i] = (d > 0.f) ? rsqrtf(d) : 0.f;
    }
}

// ---------------- fill: records (src, dis[src]) bucketed by col ----------------
__global__ void fill_kernel(const int* __restrict__ row, const int* __restrict__ col, int E) {
    int e = blockIdx.x * blockDim.x + threadIdx.x;
    if (e >= E) return;
    int r = row[e], c = col[e];
    float ds = g_dis[r];
    int pos = atomicAdd(&g_cur[c], 1);
    g_edge[pos] = make_int2(r, __float_as_int(ds));
}

// ------------- GEMM1: Y[n][0..47] = x[n][0..63] @ W1 (Y0|Y1|Y2) -------------
__global__ void gemm1_kernel(const float* __restrict__ x, const float* __restrict__ W1, int N) {
    __shared__ float sW[IN_F * 48];
    for (int t = threadIdx.x; t < 3 * IN_F * HID_F; t += blockDim.x) {
        int k = t / (IN_F * HID_F);
        int r = t % (IN_F * HID_F);
        int i = r / HID_F, j = r % HID_F;
        sW[i * 48 + k * 16 + j] = W1[t];
    }
    __syncthreads();
    int warp = threadIdx.x >> 5, lane = threadIdx.x & 31;
    int nodeBase = (blockIdx.x * 8 + warp) * 16;
    for (int nn = 0; nn < 16; nn++) {
        int node = nodeBase + nn;
        if (node >= N) return;
        const float4* xr = (const float4*)(x + (size_t)node * IN_F);
        float a0 = 0.f, a1 = 0.f;
#pragma unroll
        for (int i4 = 0; i4 < 16; i4++) {
            float4 xv = xr[i4];
            int i = i4 * 4;
            a0 += xv.x * sW[(i    ) * 48 + lane] + xv.y * sW[(i + 1) * 48 + lane]
                + xv.z * sW[(i + 2) * 48 + lane] + xv.w * sW[(i + 3) * 48 + lane];
            if (lane < 16) {
                a1 += xv.x * sW[(i    ) * 48 + 32 + lane] + xv.y * sW[(i + 1) * 48 + 32 + lane]
                    + xv.z * sW[(i + 2) * 48 + 32 + lane] + xv.w * sW[(i + 3) * 48 + 32 + lane];
            }
        }
        g_Y[(size_t)node * 48 + lane] = a0;
        if (lane < 16) g_Y[(size_t)node * 48 + 32 + lane] = a1;
    }
}

// ------------- CSR gather Lhat pass, F=16, 4 threads/node, unroll-4 -------------
// acc = (-dis[n]) * sum_e dis[src_e] * src[src_e][.]
// EPI 0: dst = acc
// EPI 1: dst = Y1 + 2*acc
// EPI 2: dst = relu(Y0 - Y2 + acc + bias)
template <int SSTR, int SOFF, int EPI>
__global__ void gather16(const float* __restrict__ src, float* __restrict__ dst,
                         const float* __restrict__ bias, int N) {
    int tid = blockIdx.x * blockDim.x + threadIdx.x;
    int n = tid >> 2;
    if (n >= N) return;
    int ch = tid & 3;
    int beg = g_off[n];
    int cnt4 = ROUND4(g_cnt[n]);
    const int2* ep = g_edge + beg;
    float ax = 0.f, ay = 0.f, az = 0.f, aw = 0.f;
    for (int i = 0; i < cnt4; i += 4) {
        int4 ra = *(const int4*)(ep + i);
        int4 rb = *(const int4*)(ep + i + 2);
        float4 v0 = *(const float4*)(src + (size_t)ra.x * SSTR + SOFF + ch * 4);
        float4 v1 = *(const float4*)(src + (size_t)ra.z * SSTR + SOFF + ch * 4);
        float4 v2 = *(const float4*)(src + (size_t)rb.x * SSTR + SOFF + ch * 4);
        float4 v3 = *(const float4*)(src + (size_t)rb.z * SSTR + SOFF + ch * 4);
        float w0 = __int_as_float(ra.y), w1 = __int_as_float(ra.w);
        float w2 = __int_as_float(rb.y), w3 = __int_as_float(rb.w);
        ax += w0 * v0.x + w1 * v1.x + w2 * v2.x + w3 * v3.x;
        ay += w0 * v0.y + w1 * v1.y + w2 * v2.y + w3 * v3.y;
        az += w0 * v0.z + w1 * v1.z + w2 * v2.z + w3 * v3.z;
        aw += w0 * v0.w + w1 * v1.w + w2 * v2.w + w3 * v3.w;
    }
    float s = -g_dis[n];
    ax *= s; ay *= s; az *= s; aw *= s;
    float4 r;
    if (EPI == 0) {
        r = make_float4(ax, ay, az, aw);
    } else if (EPI == 1) {
        float4 y1 = *(const float4*)(g_Y + (size_t)n * 48 + 16 + ch * 4);
        r = make_float4(y1.x + 2.f * ax, y1.y + 2.f * ay, y1.z + 2.f * az, y1.w + 2.f * aw);
    } else {
        float4 y0 = *(const float4*)(g_Y + (size_t)n * 48 + ch * 4);
        float4 y2 = *(const float4*)(g_Y + (size_t)n * 48 + 32 + ch * 4);
        float4 b  = *(const float4*)(bias + ch * 4);
        r.x = fmaxf(y0.x - y2.x + ax + b.x, 0.f);
        r.y = fmaxf(y0.y - y2.y + ay + b.y, 0.f);
        r.z = fmaxf(y0.z - y2.z + az + b.z, 0.f);
        r.w = fmaxf(y0.w - y2.w + aw + b.w, 0.f);
    }
    *(float4*)(dst + (size_t)n * 16 + ch * 4) = r;
}

// ------------- final fused GEMM + bias + log_softmax -------------
__global__ void final_kernel(const float* __restrict__ W2, const float* __restrict__ b2,
                             float* __restrict__ out, int N) {
    __shared__ float sW[48 * 40];
    __shared__ float sb[40];
    for (int t = threadIdx.x; t < HID_F * OUT_F; t += blockDim.x) {
        sW[t]           = W2[t] - W2[2 * 640 + t];   // W2[0]-W2[2]
        sW[16 * 40 + t] = W2[640 + t];               // W2[1]
        sW[32 * 40 + t] = 2.f * W2[2 * 640 + t];     // 2*W2[2]
    }
    if (threadIdx.x < OUT_F) sb[threadIdx.x] = b2[threadIdx.x];
    __syncthreads();

    int n = blockIdx.x * blockDim.x + threadIdx.x;
    if (n >= N) return;

    float4 acc[10];
#pragma unroll
    for (int jj = 0; jj < 10; jj++)
        acc[jj] = make_float4(sb[jj*4], sb[jj*4+1], sb[jj*4+2], sb[jj*4+3]);

    const float4* sW4 = (const float4*)sW;
    const float* srcs[3] = { g_h + (size_t)n * 16,
                             g_acc + ACC_C + (size_t)n * 16,
                             g_acc + ACC_D + (size_t)n * 16 };
#pragma unroll
    for (int b = 0; b < 3; b++) {
        float4 f4[4];
        const float4* s = (const float4*)srcs[b];
#pragma unroll
        for (int q = 0; q < 4; q++) f4[q] = s[q];
        const float* f = (const float*)f4;
#pragma unroll
        for (int i = 0; i < 16; i++) {
            float fv = f[i];
            const float4* wrow = sW4 + (b * 16 + i) * 10;
#pragma unroll
            for (int jj = 0; jj < 10; jj++) {
                float4 w = wrow[jj];
                acc[jj].x += fv * w.x; acc[jj].y += fv * w.y;
                acc[jj].z += fv * w.z; acc[jj].w += fv * w.w;
            }
        }
    }

    float* a = (float*)acc;
    float m = a[0];
#pragma unroll
    for (int j = 1; j < 40; j++) m = fmaxf(m, a[j]);
    float sum = 0.f;
#pragma unroll
    for (int j = 0; j < 40; j++) sum += __expf(a[j] - m);
    float ls = m + __logf(sum);
    float* o = out + (size_t)n * 40;
#pragma unroll
    for (int jj = 0; jj < 10; jj++) {
        float4 v = acc[jj];
        v.x -= ls; v.y -= ls; v.z -= ls; v.w -= ls;
        ((float4*)o)[jj] = v;
    }
}

// ---------------- host launcher ----------------
static float* sym_addr(const void* sym) {
    void* p = nullptr;
    cudaGetSymbolAddress(&p, sym);
    return (float*)p;
}

extern "C" void kernel_launch(void* const* d_in, const int* in_sizes, int n_in,
                              void* d_out, int out_size) {
    const float* x  = (const float*)d_in[0];
    const int*   ei = (const int*)d_in[1];
    const float* W1 = (const float*)d_in[2];
    const float* b1 = (const float*)d_in[3];
    const float* W2 = (const float*)d_in[4];
    const float* b2 = (const float*)d_in[5];
    float* out = (float*)d_out;

    int N = in_sizes[0] / IN_F;
    int E = in_sizes[1] / 2;
    if (N > NMAX) N = NMAX;
    if (E > EMAX) E = EMAX;
    const int* row = ei;
    const int* col = ei + E;

    float* p_Y   = sym_addr(g_Y);
    float* p_h   = sym_addr(g_h);
    float* p_acc = sym_addr(g_acc);

    const int T = 256;
    auto blocks = [](long n, int t) { return (int)((n + t - 1) / t); };

    // CSR build (padded segments)
    init_kernel<<<blocks(N, T), T>>>(N);
    hist_kernel<<<blocks(E, T), T>>>(row, col, E);
    alloc_kernel<<<blocks(N, T), T>>>(N);
    fill_kernel<<<blocks(E, T), T>>>(row, col, E);

    // layer 1
    gemm1_kernel<<<blocks((long)N, 128), 256>>>(x, W1, N);
    gather16<48, 32, 1><<<blocks((long)N * 4, T), T>>>(p_Y, p_acc + ACC_A, nullptr, N);          // A = Y1 + 2*Lhat(Y2)
    gather16<16, 0, 2><<<blocks((long)N * 4, T), T>>>(p_acc + ACC_A, p_h, b1, N);                // h = relu(Y0-Y2+Lhat(A)+b1)

    // layer 2
    gather16<16, 0, 0><<<blocks((long)N * 4, T), T>>>(p_h, p_acc + ACC_C, nullptr, N);           // C = Lhat(h)
    gather16<16, 0, 0><<<blocks((long)N * 4, T), T>>>(p_acc + ACC_C, p_acc + ACC_D, nullptr, N); // D = Lhat(C)
    final_kernel<<<blocks((long)N, T), T>>>(W2, b2, out, N);
}

// round 5
// speedup vs baseline: 2.0248x; 1.0444x over previous
#include <cuda_runtime.h>
#include <cuda_bf16.h>
#include <math.h>

#define NMAX 100000
#define EMAX 1600000
#define IN_F 64
#define HID_F 16
#define OUT_F 40
#define ROUND4(x) (((x) + 3) & ~3)

// ---------------- scratch (device globals: allocation-free, zero-initialized) --------
// Row NMAX of every gatherable buffer is a permanent zero row (never written):
// pad records point at it.
__device__ float g_dis[NMAX];                   // degree -> d^{-1/2}
__device__ int   g_cnt[NMAX];                   // in-degree (by col)
__device__ int4  g_meta[NMAX];                  // {off, cnt4, dis_bits, 0}
__device__ int   g_cur[NMAX];                   // fill cursors
__device__ int   g_total;                       // allocation cursor
__device__ __align__(16) int g_edge[EMAX + 4 * NMAX];   // src indices, padded segments
__device__ float g_Y[(NMAX + 1) * 48];          // U0=Y0-Y2+b1 | U1=Y1 | U2s=dis*Y2
__device__ float g_h[(NMAX + 1) * 32];          // h | hs=dis*h
__device__ float g_accA[(NMAX + 1) * 16];       // As = dis*A
__device__ float g_accC[(NMAX + 1) * 32];       // C | Cs=dis*C
__device__ float g_accD[NMAX * 16];             // D

__device__ __forceinline__ void red_add_f32(float* addr, float v) {
    asm volatile("red.global.add.f32 [%0], %1;" :: "l"(addr), "f"(v) : "memory");
}
__device__ __forceinline__ void red_add_s32(int* addr, int v) {
    asm volatile("red.global.add.s32 [%0], %1;" :: "l"(addr), "r"(v) : "memory");
}

// ---------------- init ----------------
__global__ void init_kernel(int N) {
    int i = blockIdx.x * blockDim.x + threadIdx.x;
    if (i < N) { g_dis[i] = 0.f; g_cnt[i] = 0; }
    if (i == 0) g_total = 0;
}

// ---------------- hist: out-degree (row) + in-degree (col), 4 edges/thread ----------
__global__ void hist_kernel(const int* __restrict__ row, const int* __restrict__ col, int E) {
    int base = blockIdx.x * 1024 + threadIdx.x;
#pragma unroll
    for (int k = 0; k < 4; k++) {
        int e = base + k * 256;
        if (e < E) {
            red_add_f32(&g_dis[row[e]], 1.0f);
            red_add_s32(&g_cnt[col[e]], 1);
        }
    }
}

// ---------------- alloc: warp-aggregated segment allocation + pads + dis + meta -----
__global__ void alloc_kernel(int N) {
    int i = blockIdx.x * blockDim.x + threadIdx.x;
    int lane = threadIdx.x & 31;
    int cnt = 0, cnt4 = 0;
    if (i < N) { cnt = g_cnt[i]; cnt4 = ROUND4(cnt); }
    int incl = cnt4;
#pragma unroll
    for (int d = 1; d < 32; d <<= 1) {
        int t = __shfl_up_sync(0xffffffffu, incl, d);
        if (lane >= d) incl += t;
    }
    int base = 0;
    if (lane == 31) base = atomicAdd(&g_total, incl);
    base = __shfl_sync(0xffffffffu, base, 31);
    if (i < N) {
        int off = base + incl - cnt4;
        g_cur[i] = off;
        for (int p = off + cnt; p < off + cnt4; p++) g_edge[p] = NMAX;  // zero-row pads
        float d = g_dis[i];
        float disv = (d > 0.f) ? rsqrtf(d) : 0.f;
        g_dis[i] = disv;
        g_meta[i] = make_int4(off, cnt4, __float_as_int(disv), 0);
    }
}

// ---------------- fill: src index bucketed by col, 4 edges/thread ----------------
__global__ void fill_kernel(const int* __restrict__ row, const int* __restrict__ col, int E) {
    int base = blockIdx.x * 1024 + threadIdx.x;
#pragma unroll
    for (int k = 0; k < 4; k++) {
        int e = base + k * 256;
        if (e < E) {
            int pos = atomicAdd(&g_cur[col[e]], 1);
            g_edge[pos] = row[e];
        }
    }
}

// ------------- GEMM1: per node writes U0 = Y0-Y2+b1 | U1 = Y1 | U2s = dis*Y2 ---------
__global__ void gemm1_kernel(const float* __restrict__ x, const float* __restrict__ W1,
                             const float* __restrict__ b1, int N) {
    __shared__ float sW[IN_F * 48];
    __shared__ float sb1[16];
    for (int t = threadIdx.x; t < 3 * IN_F * HID_F; t += blockDim.x) {
        int k = t / (IN_F * HID_F);
        int r = t % (IN_F * HID_F);
        int i = r / HID_F, j = r % HID_F;
        sW[i * 48 + k * 16 + j] = W1[t];
    }
    if (threadIdx.x < 16) sb1[threadIdx.x] = b1[threadIdx.x];
    __syncthreads();
    int warp = threadIdx.x >> 5, lane = threadIdx.x & 31;
    int nodeBase = (blockIdx.x * 8 + warp) * 16;
    for (int nn = 0; nn < 16; nn++) {
        int node = nodeBase + nn;
        if (node >= N) return;
        const float4* xr = (const float4*)(x + (size_t)node * IN_F);
        float a0 = 0.f, a1 = 0.f;
#pragma unroll
        for (int i4 = 0; i4 < 16; i4++) {
            float4 xv = xr[i4];
            int i = i4 * 4;
            a0 += xv.x * sW[(i    ) * 48 + lane] + xv.y * sW[(i + 1) * 48 + lane]
                + xv.z * sW[(i + 2) * 48 + lane] + xv.w * sW[(i + 3) * 48 + lane];
            if (lane < 16) {
                a1 += xv.x * sW[(i    ) * 48 + 32 + lane] + xv.y * sW[(i + 1) * 48 + 32 + lane]
                    + xv.z * sW[(i + 2) * 48 + 32 + lane] + xv.w * sW[(i + 3) * 48 + 32 + lane];
            }
        }
        float disn = g_dis[node];
        if (lane < 16) {
            g_Y[(size_t)node * 48 + lane]      = a0 - a1 + sb1[lane];  // U0
            g_Y[(size_t)node * 48 + 32 + lane] = disn * a1;            // U2s
        } else {
            g_Y[(size_t)node * 48 + lane]      = a0;                   // U1
        }
    }
}

// ------------- unweighted CSR gather, F=16, 4 threads/node -------------
// t = sum_{src in nbr} src_feat   (pads hit permanent zero row)
// EPI 1: As = dis*(U1 - 2*dis*t)             -> dst stride 16
// EPI 2: h = relu(U0 - dis*t); hs = dis*h    -> dst stride 32 (h|hs)
// EPI 3: C = -dis*t; Cs = dis*C              -> dst stride 32 (C|Cs)
// EPI 4: D = -dis*t                          -> dst stride 16
template <int SSTR, int SOFF, int EPI>
__global__ void gather16(const float* __restrict__ src, float* __restrict__ dst, int N) {
    int tid = blockIdx.x * blockDim.x + threadIdx.x;
    int n = tid >> 2;
    if (n >= N) return;
    int ch = tid & 3;
    int4 m = g_meta[n];
    const int* ep = g_edge + m.x;
    int cnt4 = m.y;
    float dis = __int_as_float(m.z);
    float ax = 0.f, ay = 0.f, az = 0.f, aw = 0.f;
#pragma unroll 2
    for (int i = 0; i < cnt4; i += 4) {
        int4 r4 = *(const int4*)(ep + i);
        float4 v0 = *(const float4*)(src + (size_t)r4.x * SSTR + SOFF + ch * 4);
        float4 v1 = *(const float4*)(src + (size_t)r4.y * SSTR + SOFF + ch * 4);
        float4 v2 = *(const float4*)(src + (size_t)r4.z * SSTR + SOFF + ch * 4);
        float4 v3 = *(const float4*)(src + (size_t)r4.w * SSTR + SOFF + ch * 4);
        ax += (v0.x + v1.x) + (v2.x + v3.x);
        ay += (v0.y + v1.y) + (v2.y + v3.y);
        az += (v0.z + v1.z) + (v2.z + v3.z);
        aw += (v0.w + v1.w) + (v2.w + v3.w);
    }
    if (EPI == 1) {
        float4 u1 = *(const float4*)(g_Y + (size_t)n * 48 + 16 + ch * 4);
        float4 r = make_float4(dis * (u1.x - 2.f * dis * ax), dis * (u1.y - 2.f * dis * ay),
                               dis * (u1.z - 2.f * dis * az), dis * (u1.w - 2.f * dis * aw));
        *(float4*)(dst + (size_t)n * 16 + ch * 4) = r;
    } else if (EPI == 2) {
        float4 u0 = *(const float4*)(g_Y + (size_t)n * 48 + ch * 4);
        float4 h = make_float4(fmaxf(u0.x - dis * ax, 0.f), fmaxf(u0.y - dis * ay, 0.f),
                               fmaxf(u0.z - dis * az, 0.f), fmaxf(u0.w - dis * aw, 0.f));
        *(float4*)(dst + (size_t)n * 32 + ch * 4) = h;
        float4 hs = make_float4(dis * h.x, dis * h.y, dis * h.z, dis * h.w);
        *(float4*)(dst + (size_t)n * 32 + 16 + ch * 4) = hs;
    } else if (EPI == 3) {
        float4 c = make_float4(-dis * ax, -dis * ay, -dis * az, -dis * aw);
        *(float4*)(dst + (size_t)n * 32 + ch * 4) = c;
        float4 cs = make_float4(dis * c.x, dis * c.y, dis * c.z, dis * c.w);
        *(float4*)(dst + (size_t)n * 32 + 16 + ch * 4) = cs;
    } else {
        float4 r = make_float4(-dis * ax, -dis * ay, -dis * az, -dis * aw);
        *(float4*)(dst + (size_t)n * 16 + ch * 4) = r;
    }
}

// ------------- final fused GEMM + bias + log_softmax -------------
__global__ void final_kernel(const float* __restrict__ W2, const float* __restrict__ b2,
                             float* __restrict__ out, int N) {
    __shared__ float sW[48 * 40];
    __shared__ float sb[40];
    for (int t = threadIdx.x; t < HID_F * OUT_F; t += blockDim.x) {
        sW[t]           = W2[t] - W2[2 * 640 + t];   // W2[0]-W2[2]
        sW[16 * 40 + t] = W2[640 + t];               // W2[1]
        sW[32 * 40 + t] = 2.f * W2[2 * 640 + t];     // 2*W2[2]
    }
    if (threadIdx.x < OUT_F) sb[threadIdx.x] = b2[threadIdx.x];
    __syncthreads();

    int n = blockIdx.x * blockDim.x + threadIdx.x;
    if (n >= N) return;

    float4 acc[10];
#pragma unroll
    for (int jj = 0; jj < 10; jj++)
        acc[jj] = make_float4(sb[jj*4], sb[jj*4+1], sb[jj*4+2], sb[jj*4+3]);

    const float4* sW4 = (const float4*)sW;
    const float* srcs[3] = { g_h    + (size_t)n * 32,
                             g_accC + (size_t)n * 32,
                             g_accD + (size_t)n * 16 };
#pragma unroll
    for (int b = 0; b < 3; b++) {
        float4 f4[4];
        const float4* s = (const float4*)srcs[b];
#pragma unroll
        for (int q = 0; q < 4; q++) f4[q] = s[q];
        const float* f = (const float*)f4;
#pragma unroll
        for (int i = 0; i < 16; i++) {
            float fv = f[i];
            const float4* wrow = sW4 + (b * 16 + i) * 10;
#pragma unroll
            for (int jj = 0; jj < 10; jj++) {
                float4 w = wrow[jj];
                acc[jj].x += fv * w.x; acc[jj].y += fv * w.y;
                acc[jj].z += fv * w.z; acc[jj].w += fv * w.w;
            }
        }
    }

    float* a = (float*)acc;
    float m = a[0];
#pragma unroll
    for (int j = 1; j < 40; j++) m = fmaxf(m, a[j]);
    float sum = 0.f;
#pragma unroll
    for (int j = 0; j < 40; j++) sum += __expf(a[j] - m);
    float ls = m + __logf(sum);
    float* o = out + (size_t)n * 40;
#pragma unroll
    for (int jj = 0; jj < 10; jj++) {
        float4 v = acc[jj];
        v.x -= ls; v.y -= ls; v.z -= ls; v.w -= ls;
        ((float4*)o)[jj] = v;
    }
}

// ---------------- host launcher ----------------
static float* sym_addr(const void* sym) {
    void* p = nullptr;
    cudaGetSymbolAddress(&p, sym);
    return (float*)p;
}

extern "C" void kernel_launch(void* const* d_in, const int* in_sizes, int n_in,
                              void* d_out, int out_size) {
    const float* x  = (const float*)d_in[0];
    const int*   ei = (const int*)d_in[1];
    const float* W1 = (const float*)d_in[2];
    const float* b1 = (const float*)d_in[3];
    const float* W2 = (const float*)d_in[4];
    const float* b2 = (const float*)d_in[5];
    float* out = (float*)d_out;

    int N = in_sizes[0] / IN_F;
    int E = in_sizes[1] / 2;
    if (N > NMAX) N = NMAX;
    if (E > EMAX) E = EMAX;
    const int* row = ei;
    const int* col = ei + E;

    float* p_Y  = sym_addr(g_Y);
    float* p_h  = sym_addr(g_h);
    float* p_A  = sym_addr(g_accA);
    float* p_C  = sym_addr(g_accC);
    float* p_D  = sym_addr(g_accD);

    const int T = 256;
    auto blocks = [](long n, int t) { return (int)((n + t - 1) / t); };

    // CSR build (padded segments, 4B records)
    init_kernel<<<blocks(N, T), T>>>(N);
    hist_kernel<<<blocks(E, 1024), T>>>(row, col, E);
    alloc_kernel<<<blocks(N, T), T>>>(N);
    fill_kernel<<<blocks(E, 1024), T>>>(row, col, E);

    // layer 1
    gemm1_kernel<<<blocks((long)N, 128), 256>>>(x, W1, b1, N);
    gather16<48, 32, 1><<<blocks((long)N * 4, T), T>>>(p_Y, p_A, N);   // As
    gather16<16, 0, 2><<<blocks((long)N * 4, T), T>>>(p_A, p_h, N);    // h | hs

    // layer 2
    gather16<32, 16, 3><<<blocks((long)N * 4, T), T>>>(p_h, p_C, N);   // C | Cs
    gather16<32, 16, 4><<<blocks((long)N * 4, T), T>>>(p_C, p_D, N);   // D
    final_kernel<<<blocks((long)N, T), T>>>(W2, b2, out, N);
}

// round 6
// speedup vs baseline: 2.3098x; 1.1408x over previous
#include <cuda_runtime.h>
#include <cuda_bf16.h>
#include <math.h>

#define NMAX 100000
#define EMAX 1600000
#define IN_F 64
#define HID_F 16
#define OUT_F 40
#define ROUND4(x) (((x) + 3) & ~3)

// ---------------- scratch (device globals: allocation-free, zero-initialized) --------
// Row NMAX of every gatherable buffer is a permanent zero row (never written):
// pad records point at it.
__device__ float g_dis[NMAX];                   // degree -> d^{-1/2}
__device__ int   g_cnt[NMAX];                   // in-degree (by col)
__device__ int4  g_meta[NMAX];                  // {off, cnt4, dis_bits, 0}
__device__ int   g_cur[NMAX];                   // fill cursors
__device__ int   g_total;                       // allocation cursor
__device__ __align__(16) int g_edge[EMAX + 4 * NMAX];   // src indices, padded segments
__device__ float g_Y[(NMAX + 1) * 48];          // U0=Y0-Y2+b1 | U1=Y1 | rawY2 -> U2s
__device__ float g_h[(NMAX + 1) * 32];          // h | hs=dis*h
__device__ float g_accA[(NMAX + 1) * 16];       // As = dis*A
__device__ float g_accC[(NMAX + 1) * 32];       // C | Cs=dis*C
__device__ float g_accD[NMAX * 16];             // D

__device__ __forceinline__ void red_add_f32(float* addr, float v) {
    asm volatile("red.global.add.f32 [%0], %1;" :: "l"(addr), "f"(v) : "memory");
}
__device__ __forceinline__ void red_add_s32(int* addr, int v) {
    asm volatile("red.global.add.s32 [%0], %1;" :: "l"(addr), "r"(v) : "memory");
}

// ---------------- init ----------------
__global__ void init_kernel(int N) {
    int i = blockIdx.x * blockDim.x + threadIdx.x;
    if (i < N) { g_dis[i] = 0.f; g_cnt[i] = 0; }
    if (i == 0) g_total = 0;
}

// ---------------- hist: out-degree (row) + in-degree (col), 8 edges/thread ----------
__global__ void hist_kernel(const int* __restrict__ row, const int* __restrict__ col, int E) {
    int base = blockIdx.x * 2048 + threadIdx.x;
#pragma unroll
    for (int k = 0; k < 8; k++) {
        int e = base + k * 256;
        if (e < E) {
            red_add_f32(&g_dis[row[e]], 1.0f);
            red_add_s32(&g_cnt[col[e]], 1);
        }
    }
}

// ---------------- alloc: warp-aggregated segment allocation + pads + dis + meta -----
__global__ void alloc_kernel(int N) {
    int i = blockIdx.x * blockDim.x + threadIdx.x;
    int lane = threadIdx.x & 31;
    int cnt = 0, cnt4 = 0;
    if (i < N) { cnt = g_cnt[i]; cnt4 = ROUND4(cnt); }
    int incl = cnt4;
#pragma unroll
    for (int d = 1; d < 32; d <<= 1) {
        int t = __shfl_up_sync(0xffffffffu, incl, d);
        if (lane >= d) incl += t;
    }
    int base = 0;
    if (lane == 31) base = atomicAdd(&g_total, incl);
    base = __shfl_sync(0xffffffffu, base, 31);
    if (i < N) {
        int off = base + incl - cnt4;
        g_cur[i] = off;
        for (int p = off + cnt; p < off + cnt4; p++) g_edge[p] = NMAX;  // zero-row pads
        float d = g_dis[i];
        float disv = (d > 0.f) ? rsqrtf(d) : 0.f;
        g_dis[i] = disv;
        g_meta[i] = make_int4(off, cnt4, __float_as_int(disv), 0);
    }
}

// ---------------- fill: src index bucketed by col, 8 edges/thread ----------------
__global__ void fill_kernel(const int* __restrict__ row, const int* __restrict__ col, int E) {
    int base = blockIdx.x * 2048 + threadIdx.x;
#pragma unroll
    for (int k = 0; k < 8; k++) {
        int e = base + k * 256;
        if (e < E) {
            int pos = atomicAdd(&g_cur[col[e]], 1);
            g_edge[pos] = row[e];
        }
    }
}

// ------------- GEMM1: per node writes U0 = Y0-Y2+b1 | U1 = Y1 | rawY2 ---------
// (independent of CSR build: no g_dis read — runs concurrently on side stream)
__global__ void gemm1_kernel(const float* __restrict__ x, const float* __restrict__ W1,
                             const float* __restrict__ b1, int N) {
    __shared__ float sW[IN_F * 48];
    __shared__ float sb1[16];
    for (int t = threadIdx.x; t < 3 * IN_F * HID_F; t += blockDim.x) {
        int k = t / (IN_F * HID_F);
        int r = t % (IN_F * HID_F);
        int i = r / HID_F, j = r % HID_F;
        sW[i * 48 + k * 16 + j] = W1[t];
    }
    if (threadIdx.x < 16) sb1[threadIdx.x] = b1[threadIdx.x];
    __syncthreads();
    int warp = threadIdx.x >> 5, lane = threadIdx.x & 31;
    int nodeBase = (blockIdx.x * 8 + warp) * 16;
    for (int nn = 0; nn < 16; nn++) {
        int node = nodeBase + nn;
        if (node >= N) return;
        const float4* xr = (const float4*)(x + (size_t)node * IN_F);
        float a0 = 0.f, a1 = 0.f;
#pragma unroll
        for (int i4 = 0; i4 < 16; i4++) {
            float4 xv = xr[i4];
            int i = i4 * 4;
            a0 += xv.x * sW[(i    ) * 48 + lane] + xv.y * sW[(i + 1) * 48 + lane]
                + xv.z * sW[(i + 2) * 48 + lane] + xv.w * sW[(i + 3) * 48 + lane];
            if (lane < 16) {
                a1 += xv.x * sW[(i    ) * 48 + 32 + lane] + xv.y * sW[(i + 1) * 48 + 32 + lane]
                    + xv.z * sW[(i + 2) * 48 + 32 + lane] + xv.w * sW[(i + 3) * 48 + 32 + lane];
            }
        }
        if (lane < 16) {
            g_Y[(size_t)node * 48 + lane]      = a0 - a1 + sb1[lane];  // U0
            g_Y[(size_t)node * 48 + 32 + lane] = a1;                   // rawY2
        } else {
            g_Y[(size_t)node * 48 + lane]      = a0;                   // U1
        }
    }
}

// ------------- scale: U2s = dis * rawY2 (after alloc + gemm1) -------------
__global__ void scale_kernel(int N) {
    int tid = blockIdx.x * blockDim.x + threadIdx.x;
    int n = tid >> 2;
    if (n >= N) return;
    int ch = tid & 3;
    float dis = g_dis[n];
    float4* p = (float4*)(g_Y + (size_t)n * 48 + 32 + ch * 4);
    float4 v = *p;
    v.x *= dis; v.y *= dis; v.z *= dis; v.w *= dis;
    *p = v;
}

// ------------- unweighted CSR gather, F=16, 4 threads/node -------------
// t = sum_{src in nbr} src_feat   (pads hit permanent zero row)
// EPI 1: As = dis*(U1 - 2*dis*t)             -> dst stride 16
// EPI 2: h = relu(U0 - dis*t); hs = dis*h    -> dst stride 32 (h|hs)
// EPI 3: C = -dis*t; Cs = dis*C              -> dst stride 32 (C|Cs)
// EPI 4: D = -dis*t                          -> dst stride 16
template <int SSTR, int SOFF, int EPI>
__global__ void gather16(const float* __restrict__ src, float* __restrict__ dst, int N) {
    int tid = blockIdx.x * blockDim.x + threadIdx.x;
    int n = tid >> 2;
    if (n >= N) return;
    int ch = tid & 3;
    int4 m = g_meta[n];
    const int* ep = g_edge + m.x;
    int cnt4 = m.y;
    float dis = __int_as_float(m.z);
    float ax = 0.f, ay = 0.f, az = 0.f, aw = 0.f;
#pragma unroll 2
    for (int i = 0; i < cnt4; i += 4) {
        int4 r4 = *(const int4*)(ep + i);
        float4 v0 = *(const float4*)(src + (size_t)r4.x * SSTR + SOFF + ch * 4);
        float4 v1 = *(const float4*)(src + (size_t)r4.y * SSTR + SOFF + ch * 4);
        float4 v2 = *(const float4*)(src + (size_t)r4.z * SSTR + SOFF + ch * 4);
        float4 v3 = *(const float4*)(src + (size_t)r4.w * SSTR + SOFF + ch * 4);
        ax += (v0.x + v1.x) + (v2.x + v3.x);
        ay += (v0.y + v1.y) + (v2.y + v3.y);
        az += (v0.z + v1.z) + (v2.z + v3.z);
        aw += (v0.w + v1.w) + (v2.w + v3.w);
    }
    if (EPI == 1) {
        float4 u1 = *(const float4*)(g_Y + (size_t)n * 48 + 16 + ch * 4);
        float4 r = make_float4(dis * (u1.x - 2.f * dis * ax), dis * (u1.y - 2.f * dis * ay),
                               dis * (u1.z - 2.f * dis * az), dis * (u1.w - 2.f * dis * aw));
        *(float4*)(dst + (size_t)n * 16 + ch * 4) = r;
    } else if (EPI == 2) {
        float4 u0 = *(const float4*)(g_Y + (size_t)n * 48 + ch * 4);
        float4 h = make_float4(fmaxf(u0.x - dis * ax, 0.f), fmaxf(u0.y - dis * ay, 0.f),
                               fmaxf(u0.z - dis * az, 0.f), fmaxf(u0.w - dis * aw, 0.f));
        *(float4*)(dst + (size_t)n * 32 + ch * 4) = h;
        float4 hs = make_float4(dis * h.x, dis * h.y, dis * h.z, dis * h.w);
        *(float4*)(dst + (size_t)n * 32 + 16 + ch * 4) = hs;
    } else if (EPI == 3) {
        float4 c = make_float4(-dis * ax, -dis * ay, -dis * az, -dis * aw);
        *(float4*)(dst + (size_t)n * 32 + ch * 4) = c;
        float4 cs = make_float4(dis * c.x, dis * c.y, dis * c.z, dis * c.w);
        *(float4*)(dst + (size_t)n * 32 + 16 + ch * 4) = cs;
    } else {
        float4 r = make_float4(-dis * ax, -dis * ay, -dis * az, -dis * aw);
        *(float4*)(dst + (size_t)n * 16 + ch * 4) = r;
    }
}

// ------------- final fused GEMM + bias + log_softmax -------------
__global__ void final_kernel(const float* __restrict__ W2, const float* __restrict__ b2,
                             float* __restrict__ out, int N) {
    __shared__ float sW[48 * 40];
    __shared__ float sb[40];
    for (int t = threadIdx.x; t < HID_F * OUT_F; t += blockDim.x) {
        sW[t]           = W2[t] - W2[2 * 640 + t];   // W2[0]-W2[2]
        sW[16 * 40 + t] = W2[640 + t];               // W2[1]
        sW[32 * 40 + t] = 2.f * W2[2 * 640 + t];     // 2*W2[2]
    }
    if (threadIdx.x < OUT_F) sb[threadIdx.x] = b2[threadIdx.x];
    __syncthreads();

    int n = blockIdx.x * blockDim.x + threadIdx.x;
    if (n >= N) return;

    float4 acc[10];
#pragma unroll
    for (int jj = 0; jj < 10; jj++)
        acc[jj] = make_float4(sb[jj*4], sb[jj*4+1], sb[jj*4+2], sb[jj*4+3]);

    const float4* sW4 = (const float4*)sW;
    const float* srcs[3] = { g_h    + (size_t)n * 32,
                             g_accC + (size_t)n * 32,
                             g_accD + (size_t)n * 16 };
#pragma unroll
    for (int b = 0; b < 3; b++) {
        float4 f4[4];
        const float4* s = (const float4*)srcs[b];
#pragma unroll
        for (int q = 0; q < 4; q++) f4[q] = s[q];
        const float* f = (const float*)f4;
#pragma unroll
        for (int i = 0; i < 16; i++) {
            float fv = f[i];
            const float4* wrow = sW4 + (b * 16 + i) * 10;
#pragma unroll
            for (int jj = 0; jj < 10; jj++) {
                float4 w = wrow[jj];
                acc[jj].x += fv * w.x; acc[jj].y += fv * w.y;
                acc[jj].z += fv * w.z; acc[jj].w += fv * w.w;
            }
        }
    }

    float* a = (float*)acc;
    float m = a[0];
#pragma unroll
    for (int j = 1; j < 40; j++) m = fmaxf(m, a[j]);
    float sum = 0.f;
#pragma unroll
    for (int j = 0; j < 40; j++) sum += __expf(a[j] - m);
    float ls = m + __logf(sum);
    float* o = out + (size_t)n * 40;
#pragma unroll
    for (int jj = 0; jj < 10; jj++) {
        float4 v = acc[jj];
        v.x -= ls; v.y -= ls; v.z -= ls; v.w -= ls;
        ((float4*)o)[jj] = v;
    }
}

// ---------------- host launcher ----------------
static float* sym_addr(const void* sym) {
    void* p = nullptr;
    cudaGetSymbolAddress(&p, sym);
    return (float*)p;
}

extern "C" void kernel_launch(void* const* d_in, const int* in_sizes, int n_in,
                              void* d_out, int out_size) {
    const float* x  = (const float*)d_in[0];
    const int*   ei = (const int*)d_in[1];
    const float* W1 = (const float*)d_in[2];
    const float* b1 = (const float*)d_in[3];
    const float* W2 = (const float*)d_in[4];
    const float* b2 = (const float*)d_in[5];
    float* out = (float*)d_out;

    int N = in_sizes[0] / IN_F;
    int E = in_sizes[1] / 2;
    if (N > NMAX) N = NMAX;
    if (E > EMAX) E = EMAX;
    const int* row = ei;
    const int* col = ei + E;

    float* p_Y  = sym_addr(g_Y);
    float* p_h  = sym_addr(g_h);
    float* p_A  = sym_addr(g_accA);
    float* p_C  = sym_addr(g_accC);
    float* p_D  = sym_addr(g_accD);

    // one-time side stream + events (host resources only; no device memory)
    static cudaStream_t s1 = nullptr;
    static cudaEvent_t evRoot = nullptr, evAlloc = nullptr, evSide = nullptr;
    if (!s1) {
        cudaStreamCreateWithFlags(&s1, cudaStreamNonBlocking);
        cudaEventCreateWithFlags(&evRoot, cudaEventDisableTiming);
        cudaEventCreateWithFlags(&evAlloc, cudaEventDisableTiming);
        cudaEventCreateWithFlags(&evSide, cudaEventDisableTiming);
    }

    const int T = 256;
    auto blocks = [](long n, int t) { return (int)((n + t - 1) / t); };

    // fork side stream
    cudaEventRecord(evRoot, 0);
    cudaStreamWaitEvent(s1, evRoot, 0);

    // side stream: GEMM1 (independent of CSR build)
    gemm1_kernel<<<blocks((long)N, 128), 256, 0, s1>>>(x, W1, b1, N);

    // main stream: CSR build (padded segments, 4B records)
    init_kernel<<<blocks(N, T), T>>>(N);
    hist_kernel<<<blocks(E, 2048), T>>>(row, col, E);
    alloc_kernel<<<blocks(N, T), T>>>(N);
    cudaEventRecord(evAlloc, 0);
    fill_kernel<<<blocks(E, 2048), T>>>(row, col, E);

    // side stream: U2s = dis * rawY2 (needs alloc's dis + gemm1)
    cudaStreamWaitEvent(s1, evAlloc, 0);
    scale_kernel<<<blocks((long)N * 4, T), T, 0, s1>>>(N);
    cudaEventRecord(evSide, s1);
    cudaStreamWaitEvent(0, evSide, 0);

    // layer 1 gathers
    gather16<48, 32, 1><<<blocks((long)N * 4, T), T>>>(p_Y, p_A, N);   // As
    gather16<16, 0, 2><<<blocks((long)N * 4, T), T>>>(p_A, p_h, N);    // h | hs

    // layer 2
    gather16<32, 16, 3><<<blocks((long)N * 4, T), T>>>(p_h, p_C, N);   // C | Cs
    gather16<32, 16, 4><<<blocks((long)N * 4, T), T>>>(p_C, p_D, N);   // D
    final_kernel<<<blocks((long)N, T), T>>>(W2, b2, out, N);
}